// round 12
// baseline (speedup 1.0000x reference)
#include <cuda_runtime.h>
#include <cuda_bf16.h>
#include <math.h>
#include <stdint.h>

// ---------------------------------------------------------------------------
// MLA forward. Split-bf16 3-term tensor-core GEMMs (Ah.Bh + Ah.Bl + Al.Bh).
// Round 12: term-major MMA ordering -- the 3 split terms for each accumulator
// are separated by 16 independent MMAs (was back-to-back RAW on the same acc
// registers), so HMMA latency is covered at 2 warps/SMSP.
// Round-11 structure retained: merged qa+kv GEMM, merged k/v GEMM into
// unified [t][320] buffer, inline causal softmax, causal block skipping,
// de-absorbed attention. PTX-stable on compute_103 (no tcgen05).
// ---------------------------------------------------------------------------

#define DIM     2048
#define N_HEADS 16
#define Q_LORA  1536
#define KV_LORA 512
#define NOPE    128
#define ROPE    64
#define V_HEAD  128
#define QK_HEAD 192
#define BATCH   2
#define SEQ     2048
#define ROWS    (BATCH * SEQ)
#define QKD     (KV_LORA + ROPE)        // 576
#define NBH     (BATCH * N_HEADS)       // 32
#define NCOMB   (Q_LORA + QKD)          // 2112
#define KVW     320                     // 128 nope + 64 rope + 128 v
#define SCALE_F 0.0721687836487032f
#define EPS_F   1e-6f

typedef __nv_bfloat16 bf16;

// ------------------------- scratch (device globals) -------------------------
__device__ __align__(256) bf16  g_xh    [(size_t)ROWS * DIM];
__device__ __align__(256) bf16  g_xl    [(size_t)ROWS * DIM];
__device__ __align__(256) bf16  g_wcombh[(size_t)NCOMB * DIM];
__device__ __align__(256) bf16  g_wcombl[(size_t)NCOMB * DIM];
__device__ __align__(256) bf16  g_wqbh  [(size_t)N_HEADS * QK_HEAD * Q_LORA];
__device__ __align__(256) bf16  g_wqbl  [(size_t)N_HEADS * QK_HEAD * Q_LORA];
__device__ __align__(256) bf16  g_wkvbh [(size_t)N_HEADS * 256 * KV_LORA];
__device__ __align__(256) bf16  g_wkvbl [(size_t)N_HEADS * 256 * KV_LORA];
__device__ __align__(256) bf16  g_woh   [(size_t)DIM * DIM];
__device__ __align__(256) bf16  g_wol   [(size_t)DIM * DIM];

__device__ __align__(256) float g_qakv_f[(size_t)ROWS * NCOMB];
__device__ __align__(256) bf16  g_qah   [(size_t)ROWS * Q_LORA];
__device__ __align__(256) bf16  g_qal   [(size_t)ROWS * Q_LORA];
__device__ __align__(256) bf16  g_qh    [(size_t)ROWS * N_HEADS * QK_HEAD];
__device__ __align__(256) bf16  g_ql    [(size_t)ROWS * N_HEADS * QK_HEAD];
__device__ __align__(256) bf16  g_kfh   [(size_t)ROWS * QKD];
__device__ __align__(256) bf16  g_kfl   [(size_t)ROWS * QKD];

__device__ __align__(256) bf16  g_kveh  [(size_t)NBH * SEQ * KVW];
__device__ __align__(256) bf16  g_kvel  [(size_t)NBH * SEQ * KVW];
__device__ __align__(256) bf16  g_vTh   [(size_t)NBH * V_HEAD * SEQ];
__device__ __align__(256) bf16  g_vTl   [(size_t)NBH * V_HEAD * SEQ];

__device__ __align__(256) float g_sc    [(size_t)NBH * SEQ * SEQ];
__device__ __align__(256) bf16  g_Ph    [(size_t)NBH * SEQ * SEQ];
__device__ __align__(256) bf16  g_Pl    [(size_t)NBH * SEQ * SEQ];
__device__ __align__(256) bf16  g_o2h   [(size_t)ROWS * DIM];
__device__ __align__(256) bf16  g_o2l   [(size_t)ROWS * DIM];

// ----------------------------- helpers --------------------------------------
__device__ __forceinline__ uint32_t smem_u32(const void* p) {
    uint32_t a;
    asm("{ .reg .u64 t; cvta.to.shared.u64 t, %1; cvt.u32.u64 %0, t; }"
        : "=r"(a) : "l"(p));
    return a;
}
__device__ __forceinline__ void cp16(uint32_t dst, const void* src) {
    asm volatile("cp.async.ca.shared.global [%0], [%1], 16;"
                 :: "r"(dst), "l"(src) : "memory");
}
#define CP_COMMIT() asm volatile("cp.async.commit_group;" ::: "memory")
#define CP_WAIT(n)  asm volatile("cp.async.wait_group %0;" :: "n"(n) : "memory")

__device__ __forceinline__ void ldm_x4(uint32_t* r, uint32_t addr) {
    asm volatile("ldmatrix.sync.aligned.m8n8.x4.shared.b16 {%0,%1,%2,%3}, [%4];"
                 : "=r"(r[0]), "=r"(r[1]), "=r"(r[2]), "=r"(r[3]) : "r"(addr));
}
__device__ __forceinline__ void mma_bf16(float* d, const uint32_t* a,
                                         const uint32_t* b) {
    asm volatile(
        "mma.sync.aligned.m16n8k16.row.col.f32.bf16.bf16.f32 "
        "{%0,%1,%2,%3}, {%4,%5,%6,%7}, {%8,%9}, {%0,%1,%2,%3};"
        : "+f"(d[0]), "+f"(d[1]), "+f"(d[2]), "+f"(d[3])
        : "r"(a[0]), "r"(a[1]), "r"(a[2]), "r"(a[3]), "r"(b[0]), "r"(b[1]));
}
__device__ __forceinline__ void bsplit(float x, bf16& h, bf16& l) {
    h = __float2bfloat16_rn(x);
    l = __float2bfloat16_rn(x - __bfloat162float(h));
}

// ----------------------- GEMM: C = alpha * A.B^T ----------------------------
// CTA tile 256x128, BK=32, 256 threads, warp tile 64x64 (4m x 2n warps).
// mode bit0: causal tile skip; bit1: causal K bound; bit2: col+=64 if col>=128
#define ROWB 80
#define AT_B (256 * ROWB)
#define BT_B (128 * ROWB)
#define STG_B (2 * AT_B + 2 * BT_B)      // 61440
#define SMEM_BYTES (2 * STG_B)           // 122880

__device__ __forceinline__ void load_tileA(uint32_t dst, const bf16* __restrict__ src,
                                           int ld, int k0, int tid) {
#pragma unroll
    for (int it = 0; it < 4; it++) {
        const int idx = tid + it * 256;
        const int row = idx >> 2, seg = idx & 3;
        cp16(dst + (uint32_t)(row * ROWB + seg * 16),
             src + (size_t)row * ld + k0 + seg * 8);
    }
}
__device__ __forceinline__ void load_tileB(uint32_t dst, const bf16* __restrict__ src,
                                           int ld, int k0, int limit, int tid) {
#pragma unroll
    for (int it = 0; it < 2; it++) {
        const int idx = tid + it * 256;
        const int row = idx >> 2, seg = idx & 3;
        const uint32_t d = dst + (uint32_t)(row * ROWB + seg * 16);
        if (row < limit) {
            cp16(d, src + (size_t)row * ld + k0 + seg * 8);
        } else {
            asm volatile("st.shared.v4.b32 [%0], {%1,%1,%1,%1};"
                         :: "r"(d), "r"(0) : "memory");
        }
    }
}
__device__ __forceinline__ void load_stage(uint32_t base,
                                           const bf16* Ath, const bf16* Atl,
                                           const bf16* Bth, const bf16* Btl,
                                           int lda, int ldb, int k0, int nlim, int tid) {
    load_tileA(base,                Ath, lda, k0, tid);
    load_tileA(base + AT_B,         Atl, lda, k0, tid);
    load_tileB(base + 2 * AT_B,        Bth, ldb, k0, nlim, tid);
    load_tileB(base + 2 * AT_B + BT_B, Btl, ldb, k0, nlim, tid);
}

template <int OUTM>
__global__ void __launch_bounds__(256)
gemm_bf3(const bf16* __restrict__ Ah, const bf16* __restrict__ Al,
         const bf16* __restrict__ Bh, const bf16* __restrict__ Bl,
         float* __restrict__ C, bf16* __restrict__ Ch, bf16* __restrict__ Cl,
         int M, int N, int K, int lda, int ldb, int ldc,
         long sAo, long sAi, long sBo, long sBi, long sCo, long sCi,
         int inner, float alpha, int mode)
{
    const int m0 = blockIdx.x * 256, n0 = blockIdx.y * 128;
    if ((mode & 1) && n0 > m0 + 128) return;

    extern __shared__ char smem[];
    const uint32_t sb = smem_u32(smem);
    const int tid = threadIdx.x, lane = tid & 31, wid = tid >> 5;
    const int wm = wid >> 1, wn = wid & 1;
    const int g = lane >> 2, tig = lane & 3;

    const int z = blockIdx.z, zo = z / inner, zi = z - zo * inner;
    const long ofA = (long)zo * sAo + (long)zi * sAi;
    const long ofB = (long)zo * sBo + (long)zi * sBi;
    const long ofC = (long)zo * sCo + (long)zi * sCi;
    Ah += ofA; Al += ofA;
    Bh += ofB; Bl += ofB;

    const bf16* Ath = Ah + (size_t)m0 * lda;
    const bf16* Atl = Al + (size_t)m0 * lda;
    const bf16* Bth = Bh + (size_t)n0 * ldb;
    const bf16* Btl = Bl + (size_t)n0 * ldb;
    const int nlim = min(128, N - n0);

    float acc[4][8][4];
#pragma unroll
    for (int i = 0; i < 4; i++)
#pragma unroll
        for (int j = 0; j < 8; j++)
#pragma unroll
            for (int r = 0; r < 4; r++) acc[i][j][r] = 0.f;

    const int Keff = (mode & 2) ? min(K, m0 + 256) : K;
    const int nch = Keff >> 5;

    load_stage(sb, Ath, Atl, Bth, Btl, lda, ldb, 0, nlim, tid);
    CP_COMMIT();

    const uint32_t aoffL = (uint32_t)((wm * 64 + (lane & 15)) * ROWB + (lane >> 4) * 16);
    const uint32_t boffL = (uint32_t)((wn * 64 + ((lane >> 4) & 1) * 8 + (lane & 7)) * ROWB
                                      + ((lane >> 3) & 1) * 16);

    for (int c = 0; c < nch; c++) {
        if (c + 1 < nch) {
            load_stage(sb + ((c + 1) & 1) * STG_B, Ath, Atl, Bth, Btl,
                       lda, ldb, (c + 1) << 5, nlim, tid);
            CP_COMMIT();
            CP_WAIT(1);
        } else {
            CP_WAIT(0);
        }
        __syncthreads();

        const uint32_t base = sb + (c & 1) * STG_B;
        const uint32_t aA = base + aoffL;
        const uint32_t bA = base + 2 * AT_B + boffL;

#pragma unroll
        for (int ks = 0; ks < 2; ks++) {
            uint32_t bh[4][4], bl[4][4];
#pragma unroll
            for (int jj = 0; jj < 4; jj++) {
                ldm_x4(bh[jj], bA + ks * 32 + jj * 16 * ROWB);
                ldm_x4(bl[jj], bA + BT_B + ks * 32 + jj * 16 * ROWB);
            }
            // process m-blocks in pairs; term-major within the pair so each
            // accumulator's 3 MMAs are 16 instructions apart (RAW covered)
#pragma unroll
            for (int ib = 0; ib < 4; ib += 2) {
                uint32_t ah[2][4], al[2][4];
#pragma unroll
                for (int u = 0; u < 2; u++) {
                    ldm_x4(ah[u], aA + ks * 32 + (ib + u) * 16 * ROWB);
                    ldm_x4(al[u], aA + AT_B + ks * 32 + (ib + u) * 16 * ROWB);
                }
                // term 1: Al.Bh
#pragma unroll
                for (int u = 0; u < 2; u++)
#pragma unroll
                    for (int j = 0; j < 8; j++)
                        mma_bf16(acc[ib + u][j], al[u], &bh[j >> 1][(j & 1) * 2]);
                // term 2: Ah.Bl
#pragma unroll
                for (int u = 0; u < 2; u++)
#pragma unroll
                    for (int j = 0; j < 8; j++)
                        mma_bf16(acc[ib + u][j], ah[u], &bl[j >> 1][(j & 1) * 2]);
                // term 3: Ah.Bh
#pragma unroll
                for (int u = 0; u < 2; u++)
#pragma unroll
                    for (int j = 0; j < 8; j++)
                        mma_bf16(acc[ib + u][j], ah[u], &bh[j >> 1][(j & 1) * 2]);
            }
        }
        __syncthreads();
    }

    // epilogue
#pragma unroll
    for (int i = 0; i < 4; i++) {
        const int r0 = m0 + wm * 64 + i * 16 + g;
#pragma unroll
        for (int j = 0; j < 8; j++) {
            const int col = n0 + wn * 64 + j * 8 + tig * 2;
            if (col >= N) continue;
            const int ocol = ((mode & 4) && col >= 128) ? col + 64 : col;
            const float c0 = alpha * acc[i][j][0], c1 = alpha * acc[i][j][1];
            const float c2 = alpha * acc[i][j][2], c3 = alpha * acc[i][j][3];
            if (OUTM == 0) {
                float* p0 = C + ofC + (size_t)r0 * ldc + ocol;
                float* p1 = C + ofC + (size_t)(r0 + 8) * ldc + ocol;
                if (col + 1 < N) {
                    *reinterpret_cast<float2*>(p0) = make_float2(c0, c1);
                    *reinterpret_cast<float2*>(p1) = make_float2(c2, c3);
                } else { p0[0] = c0; p1[0] = c2; }
            } else {
                bf16 h0, l0, h1, l1, h2, l2, h3, l3;
                bsplit(c0, h0, l0); bsplit(c1, h1, l1);
                bsplit(c2, h2, l2); bsplit(c3, h3, l3);
                *reinterpret_cast<__nv_bfloat162*>(Ch + ofC + (size_t)r0 * ldc + ocol)
                    = __nv_bfloat162(h0, h1);
                *reinterpret_cast<__nv_bfloat162*>(Cl + ofC + (size_t)r0 * ldc + ocol)
                    = __nv_bfloat162(l0, l1);
                *reinterpret_cast<__nv_bfloat162*>(Ch + ofC + (size_t)(r0 + 8) * ldc + ocol)
                    = __nv_bfloat162(h2, h3);
                *reinterpret_cast<__nv_bfloat162*>(Cl + ofC + (size_t)(r0 + 8) * ldc + ocol)
                    = __nv_bfloat162(l2, l3);
            }
        }
    }
}

// ---------------------- elementwise split f32 -> bf16 hi/lo ------------------
__global__ void __launch_bounds__(256)
split_kernel(const float* __restrict__ src, bf16* __restrict__ h,
             bf16* __restrict__ l, long n4)
{
    const long stride = (long)gridDim.x * blockDim.x;
    for (long i = blockIdx.x * (long)blockDim.x + threadIdx.x; i < n4; i += stride) {
        const float4 v = reinterpret_cast<const float4*>(src)[i];
        bf16 h0, l0, h1, l1, h2, l2, h3, l3;
        bsplit(v.x, h0, l0); bsplit(v.y, h1, l1);
        bsplit(v.z, h2, l2); bsplit(v.w, h3, l3);
        reinterpret_cast<__nv_bfloat162*>(h)[i * 2]     = __nv_bfloat162(h0, h1);
        reinterpret_cast<__nv_bfloat162*>(h)[i * 2 + 1] = __nv_bfloat162(h2, h3);
        reinterpret_cast<__nv_bfloat162*>(l)[i * 2]     = __nv_bfloat162(l0, l1);
        reinterpret_cast<__nv_bfloat162*>(l)[i * 2 + 1] = __nv_bfloat162(l2, l3);
    }
}

// ------------------- dual bf16 transpose (32x32 tiles) ----------------------
__global__ void __launch_bounds__(256)
transpose_bf2(const bf16* __restrict__ sh, const bf16* __restrict__ sl,
              bf16* __restrict__ dh, bf16* __restrict__ dl,
              int lds, int ldd, long sS, long sD)
{
    __shared__ float th[32][33], tl[32][33];
    const int z = blockIdx.z;
    sh += (long)z * sS; sl += (long)z * sS;
    dh += (long)z * sD; dl += (long)z * sD;
    const int r0 = blockIdx.x * 32, c0 = blockIdx.y * 32;
    const int tx = threadIdx.x, ty = threadIdx.y;
#pragma unroll
    for (int i = 0; i < 4; i++) {
        const long s = (long)(r0 + ty + 8 * i) * lds + c0 + tx;
        th[ty + 8 * i][tx] = __bfloat162float(sh[s]);
        tl[ty + 8 * i][tx] = __bfloat162float(sl[s]);
    }
    __syncthreads();
#pragma unroll
    for (int i = 0; i < 4; i++) {
        const long d = (long)(c0 + ty + 8 * i) * ldd + r0 + tx;
        dh[d] = __float2bfloat16_rn(th[tx][ty + 8 * i]);
        dl[d] = __float2bfloat16_rn(tl[tx][ty + 8 * i]);
    }
}

// --------------------------- rmsnorm: f32 -> split --------------------------
__global__ void __launch_bounds__(256)
rmsnorm_qa_kernel(const float* __restrict__ w)
{
    const long row = blockIdx.x;
    const float* p = g_qakv_f + row * NCOMB;
    const int tid = threadIdx.x;
    float v[6];
    float ss = 0.f;
#pragma unroll
    for (int i = 0; i < 6; i++) { v[i] = p[tid + i * 256]; ss += v[i] * v[i]; }
    __shared__ float red[256];
    red[tid] = ss; __syncthreads();
    for (int o = 128; o > 0; o >>= 1) {
        if (tid < o) red[tid] += red[tid + o];
        __syncthreads();
    }
    const float scale = rsqrtf(red[0] / (float)Q_LORA + EPS_F);
#pragma unroll
    for (int i = 0; i < 6; i++) {
        const int c = tid + i * 256;
        bf16 h, l;
        bsplit(v[i] * scale * w[c], h, l);
        g_qah[row * Q_LORA + c] = h;
        g_qal[row * Q_LORA + c] = l;
    }
}

// ------------- kv_process: qakv cols 1536:2112 -> split kf ------------------
__global__ void __launch_bounds__(256)
kv_process_kernel(const float* __restrict__ kv_norm_w,
                  const float* __restrict__ fcos,
                  const float* __restrict__ fsin)
{
    const long row = blockIdx.x;
    const int pos = (int)(row & (SEQ - 1));
    const float* src = g_qakv_f + row * NCOMB + Q_LORA;
    const int tid = threadIdx.x;

    const float v0 = src[tid], v1 = src[tid + 256];
    __shared__ float red[256];
    red[tid] = v0 * v0 + v1 * v1; __syncthreads();
    for (int o = 128; o > 0; o >>= 1) {
        if (tid < o) red[tid] += red[tid + o];
        __syncthreads();
    }
    const float scale = rsqrtf(red[0] / (float)KV_LORA + EPS_F);
    bf16 h, l;
    bsplit(v0 * scale * kv_norm_w[tid], h, l);
    g_kfh[row * QKD + tid] = h; g_kfl[row * QKD + tid] = l;
    bsplit(v1 * scale * kv_norm_w[tid + 256], h, l);
    g_kfh[row * QKD + tid + 256] = h; g_kfl[row * QKD + tid + 256] = l;

    if (tid < 32) {
        const float x0 = src[KV_LORA + 2 * tid];
        const float x1 = src[KV_LORA + 2 * tid + 1];
        const float c = fcos[pos * 32 + tid];
        const float s = fsin[pos * 32 + tid];
        bsplit(x0 * c - x1 * s, h, l);
        g_kfh[row * QKD + KV_LORA + 2 * tid] = h;
        g_kfl[row * QKD + KV_LORA + 2 * tid] = l;
        bsplit(x0 * s + x1 * c, h, l);
        g_kfh[row * QKD + KV_LORA + 2 * tid + 1] = h;
        g_kfl[row * QKD + KV_LORA + 2 * tid + 1] = l;
    }
}

// ------------- q rope (in place on split q) ---------------------------------
__global__ void __launch_bounds__(512)
q_rope_kernel(const float* __restrict__ fcos, const float* __restrict__ fsin)
{
    const long row = blockIdx.x;
    const int pos = (int)(row & (SEQ - 1));
    const int h = threadIdx.x / 32;
    const int i = threadIdx.x % 32;

    const long si = row * (N_HEADS * QK_HEAD) + h * QK_HEAD + NOPE + 2 * i;
    const float x0 = __bfloat162float(g_qh[si])     + __bfloat162float(g_ql[si]);
    const float x1 = __bfloat162float(g_qh[si + 1]) + __bfloat162float(g_ql[si + 1]);
    const float c = fcos[pos * 32 + i];
    const float s = fsin[pos * 32 + i];
    bf16 hh, ll;
    bsplit(x0 * c - x1 * s, hh, ll);
    g_qh[si] = hh; g_ql[si] = ll;
    bsplit(x0 * s + x1 * c, hh, ll);
    g_qh[si + 1] = hh; g_ql[si + 1] = ll;
}

// ------------- broadcast k_pe into kve cols 128:192 -------------------------
__global__ void __launch_bounds__(512)
kpe_fill_kernel()
{
    const long row = blockIdx.x;
    const int b = (int)(row >> 11);
    const int t = (int)(row & (SEQ - 1));
    const long src = row * QKD + KV_LORA;
#pragma unroll
    for (int it = 0; it < 2; it++) {
        const int e = threadIdx.x + it * 512;
        const int h = e >> 6, j = e & 63;
        const long dst = ((long)(b * N_HEADS + h) * SEQ + t) * KVW + NOPE + j;
        g_kveh[dst] = g_kfh[src + j];
        g_kvel[dst] = g_kfl[src + j];
    }
}

// ------------- softmax (causal mask inline, causal extent only) -------------
__global__ void __launch_bounds__(256)
softmax_mask_kernel()
{
    const long row = blockIdx.x;
    const int s = (int)(row & (SEQ - 1));
    const int T = ((s >> 7) + 1) << 7;
    const float* p = g_sc + row * SEQ;
    const int tid = threadIdx.x;
    const int t0 = tid * 8;
    const bool act = t0 < T;

    float v[8];
    float mx = -INFINITY;
    if (act) {
        const float4 a = reinterpret_cast<const float4*>(p + t0)[0];
        const float4 b = reinterpret_cast<const float4*>(p + t0)[1];
        v[0] = a.x; v[1] = a.y; v[2] = a.z; v[3] = a.w;
        v[4] = b.x; v[5] = b.y; v[6] = b.z; v[7] = b.w;
#pragma unroll
        for (int i = 0; i < 8; i++) {
            if (t0 + i > s) v[i] = -INFINITY;
            mx = fmaxf(mx, v[i]);
        }
    }
    __shared__ float red[256];
    red[tid] = mx; __syncthreads();
    for (int o = 128; o > 0; o >>= 1) {
        if (tid < o) red[tid] = fmaxf(red[tid], red[tid + o]);
        __syncthreads();
    }
    mx = red[0]; __syncthreads();

    float sum = 0.f;
    if (act) {
#pragma unroll
        for (int i = 0; i < 8; i++) { v[i] = expf(v[i] - mx); sum += v[i]; }
    }
    red[tid] = sum; __syncthreads();
    for (int o = 128; o > 0; o >>= 1) {
        if (tid < o) red[tid] += red[tid + o];
        __syncthreads();
    }
    const float inv = 1.f / red[0];

    if (act) {
#pragma unroll
        for (int i = 0; i < 4; i++) {
            bf16 h0, l0, h1, l1;
            bsplit(v[2 * i] * inv, h0, l0);
            bsplit(v[2 * i + 1] * inv, h1, l1);
            reinterpret_cast<__nv_bfloat162*>(g_Ph + row * SEQ + t0)[i]
                = __nv_bfloat162(h0, h1);
            reinterpret_cast<__nv_bfloat162*>(g_Pl + row * SEQ + t0)[i]
                = __nv_bfloat162(l0, l1);
        }
    }
}

// ---------------------------------------------------------------------------
extern "C" void kernel_launch(void* const* d_in, const int* in_sizes, int n_in,
                              void* d_out, int out_size)
{
    const float* x         = (const float*)d_in[0];
    const float* fcos      = (const float*)d_in[1];
    const float* fsin      = (const float*)d_in[2];
    // d_in[3] = mask (unused; causal mask computed inline, exact)
    const float* wq_a      = (const float*)d_in[4];
    const float* q_norm_w  = (const float*)d_in[5];
    const float* wq_b      = (const float*)d_in[6];
    const float* wkv_a     = (const float*)d_in[7];
    const float* kv_norm_w = (const float*)d_in[8];
    const float* wkv_b     = (const float*)d_in[9];
    const float* wo        = (const float*)d_in[10];
    float* out = (float*)d_out;

    bf16 *xh, *xl, *wch, *wcl, *wqbh, *wqbl, *wkvbh, *wkvbl, *woh, *wol;
    bf16 *qah, *qal, *qh, *ql, *kfh, *kfl, *kveh, *kvel, *vTh, *vTl;
    bf16 *Ph, *Pl, *o2h, *o2l;
    float *qakvf, *sc;
    cudaGetSymbolAddress((void**)&xh, g_xh);       cudaGetSymbolAddress((void**)&xl, g_xl);
    cudaGetSymbolAddress((void**)&wch, g_wcombh);  cudaGetSymbolAddress((void**)&wcl, g_wcombl);
    cudaGetSymbolAddress((void**)&wqbh, g_wqbh);   cudaGetSymbolAddress((void**)&wqbl, g_wqbl);
    cudaGetSymbolAddress((void**)&wkvbh, g_wkvbh); cudaGetSymbolAddress((void**)&wkvbl, g_wkvbl);
    cudaGetSymbolAddress((void**)&woh, g_woh);     cudaGetSymbolAddress((void**)&wol, g_wol);
    cudaGetSymbolAddress((void**)&qakvf, g_qakv_f);
    cudaGetSymbolAddress((void**)&qah, g_qah);     cudaGetSymbolAddress((void**)&qal, g_qal);
    cudaGetSymbolAddress((void**)&qh, g_qh);       cudaGetSymbolAddress((void**)&ql, g_ql);
    cudaGetSymbolAddress((void**)&kfh, g_kfh);     cudaGetSymbolAddress((void**)&kfl, g_kfl);
    cudaGetSymbolAddress((void**)&kveh, g_kveh);   cudaGetSymbolAddress((void**)&kvel, g_kvel);
    cudaGetSymbolAddress((void**)&vTh, g_vTh);     cudaGetSymbolAddress((void**)&vTl, g_vTl);
    cudaGetSymbolAddress((void**)&sc, g_sc);
    cudaGetSymbolAddress((void**)&Ph, g_Ph);       cudaGetSymbolAddress((void**)&Pl, g_Pl);
    cudaGetSymbolAddress((void**)&o2h, g_o2h);     cudaGetSymbolAddress((void**)&o2l, g_o2l);

    cudaFuncSetAttribute(gemm_bf3<0>, cudaFuncAttributeMaxDynamicSharedMemorySize, SMEM_BYTES);
    cudaFuncSetAttribute(gemm_bf3<1>, cudaFuncAttributeMaxDynamicSharedMemorySize, SMEM_BYTES);

    dim3 blk(256);
    dim3 tb(32, 8);

    // 0. split inputs + weights
    auto splits = [&](const float* s, bf16* h, bf16* l, long n) {
        const long n4 = n / 4;
        int gs = (int)min((n4 + 255) / 256, (long)4096);
        split_kernel<<<gs, blk>>>(s, h, l, n4);
    };
    splits(x,     xh,  xl,  (long)ROWS * DIM);
    splits(wq_a,  wch, wcl, (long)Q_LORA * DIM);
    splits(wkv_a, wch + (size_t)Q_LORA * DIM, wcl + (size_t)Q_LORA * DIM,
           (long)QKD * DIM);
    splits(wq_b,  wqbh, wqbl, (long)N_HEADS * QK_HEAD * Q_LORA);
    splits(wkv_b, wkvbh, wkvbl, (long)N_HEADS * 256 * KV_LORA);
    splits(wo,    woh,  wol,  (long)DIM * DIM);

    // 1. qakv = x @ [wq_a ; wkv_a]^T  (merged, f32 out)
    gemm_bf3<0><<<dim3(ROWS/256, (NCOMB + 127)/128, 1), blk, SMEM_BYTES>>>(
        xh, xl, wch, wcl, qakvf, nullptr, nullptr,
        ROWS, NCOMB, DIM, DIM, DIM, NCOMB, 0,0, 0,0, 0,0, 1, 1.f, 0);

    // 2. norms
    rmsnorm_qa_kernel<<<ROWS, blk>>>(q_norm_w);
    kv_process_kernel<<<ROWS, blk>>>(kv_norm_w, fcos, fsin);

    // 3. q = qa @ wq_b^T (split out)
    gemm_bf3<1><<<dim3(ROWS/256, (N_HEADS*QK_HEAD)/128, 1), blk, SMEM_BYTES>>>(
        qah, qal, wqbh, wqbl, nullptr, qh, ql,
        ROWS, N_HEADS*QK_HEAD, Q_LORA, Q_LORA, Q_LORA, N_HEADS*QK_HEAD,
        0,0, 0,0, 0,0, 1, 1.f, 0);

    // 4. rope(q_pe) in place
    q_rope_kernel<<<ROWS, 512>>>(fcos, fsin);

    // 5. kve = kf_c @ wkvb^T  (merged k/v, split out, col shift)
    gemm_bf3<1><<<dim3(SEQ/256, 2, NBH), blk, SMEM_BYTES>>>(
        kfh, kfl, wkvbh, wkvbl, nullptr, kveh, kvel,
        SEQ, 256, KV_LORA, QKD, KV_LORA, KVW,
        (long)SEQ*QKD, 0,
        0, (long)256*KV_LORA,
        (long)N_HEADS*SEQ*KVW, (long)SEQ*KVW,
        N_HEADS, 1.f, 4);

    // 6. broadcast k_pe
    kpe_fill_kernel<<<ROWS, 512>>>();

    // 7. transpose v -> vT
    transpose_bf2<<<dim3(SEQ/32, V_HEAD/32, NBH), tb>>>(
        kveh + 192, kvel + 192, vTh, vTl, KVW, SEQ,
        (long)SEQ*KVW, (long)V_HEAD*SEQ);

    // 8. scores (K=192, causal tiles only)
    gemm_bf3<0><<<dim3(SEQ/256, SEQ/128, NBH), blk, SMEM_BYTES>>>(
        qh, ql, kveh, kvel, sc, nullptr, nullptr,
        SEQ, SEQ, QK_HEAD, N_HEADS*QK_HEAD, KVW, SEQ,
        (long)SEQ*N_HEADS*QK_HEAD, QK_HEAD,
        (long)N_HEADS*SEQ*KVW, (long)SEQ*KVW,
        (long)N_HEADS*SEQ*SEQ, (long)SEQ*SEQ,
        N_HEADS, SCALE_F, 1);

    // 9. softmax (causal inline)
    softmax_mask_kernel<<<NBH*SEQ, blk>>>();

    // 10. o2 = P @ vT^T  (causal K bound)
    gemm_bf3<1><<<dim3(SEQ/256, 1, NBH), blk, SMEM_BYTES>>>(
        Ph, Pl, vTh, vTl, nullptr, o2h, o2l,
        SEQ, V_HEAD, SEQ, SEQ, SEQ, DIM,
        (long)N_HEADS*SEQ*SEQ, (long)SEQ*SEQ,
        (long)N_HEADS*V_HEAD*SEQ, (long)V_HEAD*SEQ,
        (long)SEQ*DIM, V_HEAD,
        N_HEADS, 1.f, 2);

    // 11. out = o2 @ wo^T  (f32 out)
    gemm_bf3<0><<<dim3(ROWS/256, DIM/128, 1), blk, SMEM_BYTES>>>(
        o2h, o2l, woh, wol, out, nullptr, nullptr,
        ROWS, DIM, DIM, DIM, DIM, DIM, 0,0, 0,0, 0,0, 1, 1.f, 0);
}

// round 13
// speedup vs baseline: 1.0211x; 1.0211x over previous
#include <cuda_runtime.h>
#include <cuda_bf16.h>
#include <math.h>
#include <stdint.h>

// ---------------------------------------------------------------------------
// MLA forward. Split-bf16 3-term tensor-core GEMMs (Ah.Bh + Ah.Bl + Al.Bh).
// Round 13: softmax fused away.
//  - scores GEMM epilogue computes exp(SCALE*s) (causal-masked, no max
//    subtraction -- logits are O(4), fp32 exp safe), writes split-bf16
//    unnormalized P, and emits DETERMINISTIC per-(row, n-tile) partial sums.
//  - tiny combine kernel -> inv_rowsum; P.V epilogue scales by it.
//  - f32 scores buffer and softmax kernel eliminated (571MB round trip).
// Round-11 structure retained otherwise. PTX-stable on compute_103.
// ---------------------------------------------------------------------------

#define DIM     2048
#define N_HEADS 16
#define Q_LORA  1536
#define KV_LORA 512
#define NOPE    128
#define ROPE    64
#define V_HEAD  128
#define QK_HEAD 192
#define BATCH   2
#define SEQ     2048
#define ROWS    (BATCH * SEQ)
#define QKD     (KV_LORA + ROPE)        // 576
#define NBH     (BATCH * N_HEADS)       // 32
#define NCOMB   (Q_LORA + QKD)          // 2112
#define KVW     320                     // 128 nope + 64 rope + 128 v
#define SCALE_F 0.0721687836487032f
#define EPS_F   1e-6f

typedef __nv_bfloat16 bf16;

// ------------------------- scratch (device globals) -------------------------
__device__ __align__(256) bf16  g_xh    [(size_t)ROWS * DIM];
__device__ __align__(256) bf16  g_xl    [(size_t)ROWS * DIM];
__device__ __align__(256) bf16  g_wcombh[(size_t)NCOMB * DIM];
__device__ __align__(256) bf16  g_wcombl[(size_t)NCOMB * DIM];
__device__ __align__(256) bf16  g_wqbh  [(size_t)N_HEADS * QK_HEAD * Q_LORA];
__device__ __align__(256) bf16  g_wqbl  [(size_t)N_HEADS * QK_HEAD * Q_LORA];
__device__ __align__(256) bf16  g_wkvbh [(size_t)N_HEADS * 256 * KV_LORA];
__device__ __align__(256) bf16  g_wkvbl [(size_t)N_HEADS * 256 * KV_LORA];
__device__ __align__(256) bf16  g_woh   [(size_t)DIM * DIM];
__device__ __align__(256) bf16  g_wol   [(size_t)DIM * DIM];

__device__ __align__(256) float g_qakv_f[(size_t)ROWS * NCOMB];
__device__ __align__(256) bf16  g_qah   [(size_t)ROWS * Q_LORA];
__device__ __align__(256) bf16  g_qal   [(size_t)ROWS * Q_LORA];
__device__ __align__(256) bf16  g_qh    [(size_t)ROWS * N_HEADS * QK_HEAD];
__device__ __align__(256) bf16  g_ql    [(size_t)ROWS * N_HEADS * QK_HEAD];
__device__ __align__(256) bf16  g_kfh   [(size_t)ROWS * QKD];
__device__ __align__(256) bf16  g_kfl   [(size_t)ROWS * QKD];

__device__ __align__(256) bf16  g_kveh  [(size_t)NBH * SEQ * KVW];
__device__ __align__(256) bf16  g_kvel  [(size_t)NBH * SEQ * KVW];
__device__ __align__(256) bf16  g_vTh   [(size_t)NBH * V_HEAD * SEQ];
__device__ __align__(256) bf16  g_vTl   [(size_t)NBH * V_HEAD * SEQ];

__device__ __align__(256) bf16  g_Ph    [(size_t)NBH * SEQ * SEQ];
__device__ __align__(256) bf16  g_Pl    [(size_t)NBH * SEQ * SEQ];
__device__ __align__(256) float g_ps    [(size_t)NBH * SEQ * 16];   // partial sums
__device__ __align__(256) float g_inv   [(size_t)NBH * SEQ];        // 1/rowsum
__device__ __align__(256) bf16  g_o2h   [(size_t)ROWS * DIM];
__device__ __align__(256) bf16  g_o2l   [(size_t)ROWS * DIM];

// ----------------------------- helpers --------------------------------------
__device__ __forceinline__ uint32_t smem_u32(const void* p) {
    uint32_t a;
    asm("{ .reg .u64 t; cvta.to.shared.u64 t, %1; cvt.u32.u64 %0, t; }"
        : "=r"(a) : "l"(p));
    return a;
}
__device__ __forceinline__ void cp16(uint32_t dst, const void* src) {
    asm volatile("cp.async.ca.shared.global [%0], [%1], 16;"
                 :: "r"(dst), "l"(src) : "memory");
}
#define CP_COMMIT() asm volatile("cp.async.commit_group;" ::: "memory")
#define CP_WAIT(n)  asm volatile("cp.async.wait_group %0;" :: "n"(n) : "memory")

__device__ __forceinline__ void ldm_x4(uint32_t* r, uint32_t addr) {
    asm volatile("ldmatrix.sync.aligned.m8n8.x4.shared.b16 {%0,%1,%2,%3}, [%4];"
                 : "=r"(r[0]), "=r"(r[1]), "=r"(r[2]), "=r"(r[3]) : "r"(addr));
}
__device__ __forceinline__ void mma_bf16(float* d, const uint32_t* a,
                                         const uint32_t* b) {
    asm volatile(
        "mma.sync.aligned.m16n8k16.row.col.f32.bf16.bf16.f32 "
        "{%0,%1,%2,%3}, {%4,%5,%6,%7}, {%8,%9}, {%0,%1,%2,%3};"
        : "+f"(d[0]), "+f"(d[1]), "+f"(d[2]), "+f"(d[3])
        : "r"(a[0]), "r"(a[1]), "r"(a[2]), "r"(a[3]), "r"(b[0]), "r"(b[1]));
}
__device__ __forceinline__ void bsplit(float x, bf16& h, bf16& l) {
    h = __float2bfloat16_rn(x);
    l = __float2bfloat16_rn(x - __bfloat162float(h));
}

// ----------------------- GEMM: C = alpha * A.B^T ----------------------------
// CTA tile 256x128, BK=32, 256 threads, warp tile 64x64 (4m x 2n warps).
// OUTM=0: C f32. OUTM=1: split bf16 (C may carry inv-rowsum, mode bit3).
// OUTM=2: exp epilogue -> split bf16 P + per-(row,ntile) partial sums in C.
// mode bit0: causal tile skip; bit1: causal K bound;
// bit2: col+=64 if col>=128 (unified k/v layout); bit3: scale rows by C[row].
#define ROWB 80
#define AT_B (256 * ROWB)
#define BT_B (128 * ROWB)
#define STG_B (2 * AT_B + 2 * BT_B)      // 61440
#define SMEM_BYTES (2 * STG_B)           // 122880

__device__ __forceinline__ void load_tileA(uint32_t dst, const bf16* __restrict__ src,
                                           int ld, int k0, int tid) {
#pragma unroll
    for (int it = 0; it < 4; it++) {
        const int idx = tid + it * 256;
        const int row = idx >> 2, seg = idx & 3;
        cp16(dst + (uint32_t)(row * ROWB + seg * 16),
             src + (size_t)row * ld + k0 + seg * 8);
    }
}
__device__ __forceinline__ void load_tileB(uint32_t dst, const bf16* __restrict__ src,
                                           int ld, int k0, int limit, int tid) {
#pragma unroll
    for (int it = 0; it < 2; it++) {
        const int idx = tid + it * 256;
        const int row = idx >> 2, seg = idx & 3;
        const uint32_t d = dst + (uint32_t)(row * ROWB + seg * 16);
        if (row < limit) {
            cp16(d, src + (size_t)row * ld + k0 + seg * 8);
        } else {
            asm volatile("st.shared.v4.b32 [%0], {%1,%1,%1,%1};"
                         :: "r"(d), "r"(0) : "memory");
        }
    }
}
__device__ __forceinline__ void load_stage(uint32_t base,
                                           const bf16* Ath, const bf16* Atl,
                                           const bf16* Bth, const bf16* Btl,
                                           int lda, int ldb, int k0, int nlim, int tid) {
    load_tileA(base,                Ath, lda, k0, tid);
    load_tileA(base + AT_B,         Atl, lda, k0, tid);
    load_tileB(base + 2 * AT_B,        Bth, ldb, k0, nlim, tid);
    load_tileB(base + 2 * AT_B + BT_B, Btl, ldb, k0, nlim, tid);
}

template <int OUTM>
__global__ void __launch_bounds__(256)
gemm_bf3(const bf16* __restrict__ Ah, const bf16* __restrict__ Al,
         const bf16* __restrict__ Bh, const bf16* __restrict__ Bl,
         float* __restrict__ C, bf16* __restrict__ Ch, bf16* __restrict__ Cl,
         int M, int N, int K, int lda, int ldb, int ldc,
         long sAo, long sAi, long sBo, long sBi, long sCo, long sCi,
         int inner, float alpha, int mode)
{
    const int m0 = blockIdx.x * 256, n0 = blockIdx.y * 128;
    if ((mode & 1) && n0 > m0 + 128) return;

    extern __shared__ char smem[];
    __shared__ float sred[2][256];
    const uint32_t sb = smem_u32(smem);
    const int tid = threadIdx.x, lane = tid & 31, wid = tid >> 5;
    const int wm = wid >> 1, wn = wid & 1;
    const int g = lane >> 2, tig = lane & 3;

    const int z = blockIdx.z, zo = z / inner, zi = z - zo * inner;
    const long ofA = (long)zo * sAo + (long)zi * sAi;
    const long ofB = (long)zo * sBo + (long)zi * sBi;
    const long ofC = (long)zo * sCo + (long)zi * sCi;
    Ah += ofA; Al += ofA;
    Bh += ofB; Bl += ofB;

    const bf16* Ath = Ah + (size_t)m0 * lda;
    const bf16* Atl = Al + (size_t)m0 * lda;
    const bf16* Bth = Bh + (size_t)n0 * ldb;
    const bf16* Btl = Bl + (size_t)n0 * ldb;
    const int nlim = min(128, N - n0);

    float acc[4][8][4];
#pragma unroll
    for (int i = 0; i < 4; i++)
#pragma unroll
        for (int j = 0; j < 8; j++)
#pragma unroll
            for (int r = 0; r < 4; r++) acc[i][j][r] = 0.f;

    const int Keff = (mode & 2) ? min(K, m0 + 256) : K;
    const int nch = Keff >> 5;

    load_stage(sb, Ath, Atl, Bth, Btl, lda, ldb, 0, nlim, tid);
    CP_COMMIT();

    const uint32_t aoffL = (uint32_t)((wm * 64 + (lane & 15)) * ROWB + (lane >> 4) * 16);
    const uint32_t boffL = (uint32_t)((wn * 64 + ((lane >> 4) & 1) * 8 + (lane & 7)) * ROWB
                                      + ((lane >> 3) & 1) * 16);

    for (int c = 0; c < nch; c++) {
        if (c + 1 < nch) {
            load_stage(sb + ((c + 1) & 1) * STG_B, Ath, Atl, Bth, Btl,
                       lda, ldb, (c + 1) << 5, nlim, tid);
            CP_COMMIT();
            CP_WAIT(1);
        } else {
            CP_WAIT(0);
        }
        __syncthreads();

        const uint32_t base = sb + (c & 1) * STG_B;
        const uint32_t aA = base + aoffL;
        const uint32_t bA = base + 2 * AT_B + boffL;

#pragma unroll
        for (int ks = 0; ks < 2; ks++) {
            uint32_t bh[4][4], bl[4][4];
#pragma unroll
            for (int jj = 0; jj < 4; jj++) {
                ldm_x4(bh[jj], bA + ks * 32 + jj * 16 * ROWB);
                ldm_x4(bl[jj], bA + BT_B + ks * 32 + jj * 16 * ROWB);
            }
#pragma unroll
            for (int i = 0; i < 4; i++) {
                uint32_t ahf[4], alf[4];
                ldm_x4(ahf, aA + ks * 32 + i * 16 * ROWB);
                ldm_x4(alf, aA + AT_B + ks * 32 + i * 16 * ROWB);
#pragma unroll
                for (int j = 0; j < 8; j++) {
                    const uint32_t* bhp = &bh[j >> 1][(j & 1) * 2];
                    const uint32_t* blp = &bl[j >> 1][(j & 1) * 2];
                    mma_bf16(acc[i][j], alf, bhp);
                    mma_bf16(acc[i][j], ahf, blp);
                    mma_bf16(acc[i][j], ahf, bhp);
                }
            }
        }
        __syncthreads();
    }

    if (OUTM == 2) {
        // exp epilogue: unnormalized softmax numerators + deterministic
        // per-(row, n-tile) partial sums. M == SEQ here; r0 is the s index.
        float* ps = C + (size_t)z * SEQ * 16;
        const int ntile = n0 >> 7;
#pragma unroll
        for (int i = 0; i < 4; i++) {
            const int r0 = m0 + wm * 64 + i * 16 + g;
            float s0 = 0.f, s1 = 0.f;
#pragma unroll
            for (int j = 0; j < 8; j++) {
                const int col = n0 + wn * 64 + j * 8 + tig * 2;
                const float e0 = (col     <= r0)     ? __expf(alpha * acc[i][j][0]) : 0.f;
                const float e1 = (col + 1 <= r0)     ? __expf(alpha * acc[i][j][1]) : 0.f;
                const float e2 = (col     <= r0 + 8) ? __expf(alpha * acc[i][j][2]) : 0.f;
                const float e3 = (col + 1 <= r0 + 8) ? __expf(alpha * acc[i][j][3]) : 0.f;
                s0 += e0 + e1; s1 += e2 + e3;
                bf16 h0, l0, h1, l1, h2, l2, h3, l3;
                bsplit(e0, h0, l0); bsplit(e1, h1, l1);
                bsplit(e2, h2, l2); bsplit(e3, h3, l3);
                *reinterpret_cast<__nv_bfloat162*>(Ch + ofC + (size_t)r0 * ldc + col)
                    = __nv_bfloat162(h0, h1);
                *reinterpret_cast<__nv_bfloat162*>(Cl + ofC + (size_t)r0 * ldc + col)
                    = __nv_bfloat162(l0, l1);
                *reinterpret_cast<__nv_bfloat162*>(Ch + ofC + (size_t)(r0 + 8) * ldc + col)
                    = __nv_bfloat162(h2, h3);
                *reinterpret_cast<__nv_bfloat162*>(Cl + ofC + (size_t)(r0 + 8) * ldc + col)
                    = __nv_bfloat162(l2, l3);
            }
            // deterministic reduce over the 4 tig lanes
            s0 += __shfl_xor_sync(0xffffffffu, s0, 1);
            s0 += __shfl_xor_sync(0xffffffffu, s0, 2);
            s1 += __shfl_xor_sync(0xffffffffu, s1, 1);
            s1 += __shfl_xor_sync(0xffffffffu, s1, 2);
            if (tig == 0) {
                sred[wn][wm * 64 + i * 16 + g]     = s0;
                sred[wn][wm * 64 + i * 16 + g + 8] = s1;
            }
        }
        __syncthreads();
        // one partial per row per n-tile, fixed combine order
        ps[(size_t)(m0 + tid) * 16 + ntile] = sred[0][tid] + sred[1][tid];
        return;
    }

    // standard epilogues
#pragma unroll
    for (int i = 0; i < 4; i++) {
        const int r0 = m0 + wm * 64 + i * 16 + g;
        float sc0 = alpha, sc1 = alpha;
        if (OUTM == 1 && (mode & 8)) {
            const float* invp = C + (size_t)z * SEQ;
            sc0 = invp[r0]; sc1 = invp[r0 + 8];
        }
#pragma unroll
        for (int j = 0; j < 8; j++) {
            const int col = n0 + wn * 64 + j * 8 + tig * 2;
            if (col >= N) continue;
            const int ocol = ((mode & 4) && col >= 128) ? col + 64 : col;
            const float c0 = sc0 * acc[i][j][0], c1 = sc0 * acc[i][j][1];
            const float c2 = sc1 * acc[i][j][2], c3 = sc1 * acc[i][j][3];
            if (OUTM == 0) {
                float* p0 = C + ofC + (size_t)r0 * ldc + ocol;
                float* p1 = C + ofC + (size_t)(r0 + 8) * ldc + ocol;
                if (col + 1 < N) {
                    *reinterpret_cast<float2*>(p0) = make_float2(c0, c1);
                    *reinterpret_cast<float2*>(p1) = make_float2(c2, c3);
                } else { p0[0] = c0; p1[0] = c2; }
            } else {
                bf16 h0, l0, h1, l1, h2, l2, h3, l3;
                bsplit(c0, h0, l0); bsplit(c1, h1, l1);
                bsplit(c2, h2, l2); bsplit(c3, h3, l3);
                *reinterpret_cast<__nv_bfloat162*>(Ch + ofC + (size_t)r0 * ldc + ocol)
                    = __nv_bfloat162(h0, h1);
                *reinterpret_cast<__nv_bfloat162*>(Cl + ofC + (size_t)r0 * ldc + ocol)
                    = __nv_bfloat162(l0, l1);
                *reinterpret_cast<__nv_bfloat162*>(Ch + ofC + (size_t)(r0 + 8) * ldc + ocol)
                    = __nv_bfloat162(h2, h3);
                *reinterpret_cast<__nv_bfloat162*>(Cl + ofC + (size_t)(r0 + 8) * ldc + ocol)
                    = __nv_bfloat162(l2, l3);
            }
        }
    }
}

// ----------------- combine partial sums -> inverse row sums -----------------
__global__ void __launch_bounds__(256)
rowsum_combine_kernel()
{
    const long row = (long)blockIdx.x * 256 + threadIdx.x;  // [bh][s]
    const int s = (int)(row & (SEQ - 1));
    const int nt = 2 * (s >> 8) + 2;          // tiles written for this row
    const float* ps = g_ps + row * 16;
    float sum = 0.f;
    for (int j = 0; j < nt; j++) sum += ps[j];
    g_inv[row] = 1.0f / sum;
}

// ---------------------- elementwise split f32 -> bf16 hi/lo ------------------
__global__ void __launch_bounds__(256)
split_kernel(const float* __restrict__ src, bf16* __restrict__ h,
             bf16* __restrict__ l, long n4)
{
    const long stride = (long)gridDim.x * blockDim.x;
    for (long i = blockIdx.x * (long)blockDim.x + threadIdx.x; i < n4; i += stride) {
        const float4 v = reinterpret_cast<const float4*>(src)[i];
        bf16 h0, l0, h1, l1, h2, l2, h3, l3;
        bsplit(v.x, h0, l0); bsplit(v.y, h1, l1);
        bsplit(v.z, h2, l2); bsplit(v.w, h3, l3);
        reinterpret_cast<__nv_bfloat162*>(h)[i * 2]     = __nv_bfloat162(h0, h1);
        reinterpret_cast<__nv_bfloat162*>(h)[i * 2 + 1] = __nv_bfloat162(h2, h3);
        reinterpret_cast<__nv_bfloat162*>(l)[i * 2]     = __nv_bfloat162(l0, l1);
        reinterpret_cast<__nv_bfloat162*>(l)[i * 2 + 1] = __nv_bfloat162(l2, l3);
    }
}

// ------------------- dual bf16 transpose (32x32 tiles) ----------------------
__global__ void __launch_bounds__(256)
transpose_bf2(const bf16* __restrict__ sh, const bf16* __restrict__ sl,
              bf16* __restrict__ dh, bf16* __restrict__ dl,
              int lds, int ldd, long sS, long sD)
{
    __shared__ float th[32][33], tl[32][33];
    const int z = blockIdx.z;
    sh += (long)z * sS; sl += (long)z * sS;
    dh += (long)z * sD; dl += (long)z * sD;
    const int r0 = blockIdx.x * 32, c0 = blockIdx.y * 32;
    const int tx = threadIdx.x, ty = threadIdx.y;
#pragma unroll
    for (int i = 0; i < 4; i++) {
        const long s = (long)(r0 + ty + 8 * i) * lds + c0 + tx;
        th[ty + 8 * i][tx] = __bfloat162float(sh[s]);
        tl[ty + 8 * i][tx] = __bfloat162float(sl[s]);
    }
    __syncthreads();
#pragma unroll
    for (int i = 0; i < 4; i++) {
        const long d = (long)(c0 + ty + 8 * i) * ldd + r0 + tx;
        dh[d] = __float2bfloat16_rn(th[tx][ty + 8 * i]);
        dl[d] = __float2bfloat16_rn(tl[tx][ty + 8 * i]);
    }
}

// --------------------------- rmsnorm: f32 -> split --------------------------
__global__ void __launch_bounds__(256)
rmsnorm_qa_kernel(const float* __restrict__ w)
{
    const long row = blockIdx.x;
    const float* p = g_qakv_f + row * NCOMB;
    const int tid = threadIdx.x;
    float v[6];
    float ss = 0.f;
#pragma unroll
    for (int i = 0; i < 6; i++) { v[i] = p[tid + i * 256]; ss += v[i] * v[i]; }
    __shared__ float red[256];
    red[tid] = ss; __syncthreads();
    for (int o = 128; o > 0; o >>= 1) {
        if (tid < o) red[tid] += red[tid + o];
        __syncthreads();
    }
    const float scale = rsqrtf(red[0] / (float)Q_LORA + EPS_F);
#pragma unroll
    for (int i = 0; i < 6; i++) {
        const int c = tid + i * 256;
        bf16 h, l;
        bsplit(v[i] * scale * w[c], h, l);
        g_qah[row * Q_LORA + c] = h;
        g_qal[row * Q_LORA + c] = l;
    }
}

// ------------- kv_process: qakv cols 1536:2112 -> split kf ------------------
__global__ void __launch_bounds__(256)
kv_process_kernel(const float* __restrict__ kv_norm_w,
                  const float* __restrict__ fcos,
                  const float* __restrict__ fsin)
{
    const long row = blockIdx.x;
    const int pos = (int)(row & (SEQ - 1));
    const float* src = g_qakv_f + row * NCOMB + Q_LORA;
    const int tid = threadIdx.x;

    const float v0 = src[tid], v1 = src[tid + 256];
    __shared__ float red[256];
    red[tid] = v0 * v0 + v1 * v1; __syncthreads();
    for (int o = 128; o > 0; o >>= 1) {
        if (tid < o) red[tid] += red[tid + o];
        __syncthreads();
    }
    const float scale = rsqrtf(red[0] / (float)KV_LORA + EPS_F);
    bf16 h, l;
    bsplit(v0 * scale * kv_norm_w[tid], h, l);
    g_kfh[row * QKD + tid] = h; g_kfl[row * QKD + tid] = l;
    bsplit(v1 * scale * kv_norm_w[tid + 256], h, l);
    g_kfh[row * QKD + tid + 256] = h; g_kfl[row * QKD + tid + 256] = l;

    if (tid < 32) {
        const float x0 = src[KV_LORA + 2 * tid];
        const float x1 = src[KV_LORA + 2 * tid + 1];
        const float c = fcos[pos * 32 + tid];
        const float s = fsin[pos * 32 + tid];
        bsplit(x0 * c - x1 * s, h, l);
        g_kfh[row * QKD + KV_LORA + 2 * tid] = h;
        g_kfl[row * QKD + KV_LORA + 2 * tid] = l;
        bsplit(x0 * s + x1 * c, h, l);
        g_kfh[row * QKD + KV_LORA + 2 * tid + 1] = h;
        g_kfl[row * QKD + KV_LORA + 2 * tid + 1] = l;
    }
}

// ------------- q rope (in place on split q) ---------------------------------
__global__ void __launch_bounds__(512)
q_rope_kernel(const float* __restrict__ fcos, const float* __restrict__ fsin)
{
    const long row = blockIdx.x;
    const int pos = (int)(row & (SEQ - 1));
    const int h = threadIdx.x / 32;
    const int i = threadIdx.x % 32;

    const long si = row * (N_HEADS * QK_HEAD) + h * QK_HEAD + NOPE + 2 * i;
    const float x0 = __bfloat162float(g_qh[si])     + __bfloat162float(g_ql[si]);
    const float x1 = __bfloat162float(g_qh[si + 1]) + __bfloat162float(g_ql[si + 1]);
    const float c = fcos[pos * 32 + i];
    const float s = fsin[pos * 32 + i];
    bf16 hh, ll;
    bsplit(x0 * c - x1 * s, hh, ll);
    g_qh[si] = hh; g_ql[si] = ll;
    bsplit(x0 * s + x1 * c, hh, ll);
    g_qh[si + 1] = hh; g_ql[si + 1] = ll;
}

// ------------- broadcast k_pe into kve cols 128:192 -------------------------
__global__ void __launch_bounds__(512)
kpe_fill_kernel()
{
    const long row = blockIdx.x;
    const int b = (int)(row >> 11);
    const int t = (int)(row & (SEQ - 1));
    const long src = row * QKD + KV_LORA;
#pragma unroll
    for (int it = 0; it < 2; it++) {
        const int e = threadIdx.x + it * 512;
        const int h = e >> 6, j = e & 63;
        const long dst = ((long)(b * N_HEADS + h) * SEQ + t) * KVW + NOPE + j;
        g_kveh[dst] = g_kfh[src + j];
        g_kvel[dst] = g_kfl[src + j];
    }
}

// ---------------------------------------------------------------------------
extern "C" void kernel_launch(void* const* d_in, const int* in_sizes, int n_in,
                              void* d_out, int out_size)
{
    const float* x         = (const float*)d_in[0];
    const float* fcos      = (const float*)d_in[1];
    const float* fsin      = (const float*)d_in[2];
    // d_in[3] = mask (unused; causal mask computed inline, exact)
    const float* wq_a      = (const float*)d_in[4];
    const float* q_norm_w  = (const float*)d_in[5];
    const float* wq_b      = (const float*)d_in[6];
    const float* wkv_a     = (const float*)d_in[7];
    const float* kv_norm_w = (const float*)d_in[8];
    const float* wkv_b     = (const float*)d_in[9];
    const float* wo        = (const float*)d_in[10];
    float* out = (float*)d_out;

    bf16 *xh, *xl, *wch, *wcl, *wqbh, *wqbl, *wkvbh, *wkvbl, *woh, *wol;
    bf16 *qah, *qal, *qh, *ql, *kfh, *kfl, *kveh, *kvel, *vTh, *vTl;
    bf16 *Ph, *Pl, *o2h, *o2l;
    float *qakvf, *ps, *inv;
    cudaGetSymbolAddress((void**)&xh, g_xh);       cudaGetSymbolAddress((void**)&xl, g_xl);
    cudaGetSymbolAddress((void**)&wch, g_wcombh);  cudaGetSymbolAddress((void**)&wcl, g_wcombl);
    cudaGetSymbolAddress((void**)&wqbh, g_wqbh);   cudaGetSymbolAddress((void**)&wqbl, g_wqbl);
    cudaGetSymbolAddress((void**)&wkvbh, g_wkvbh); cudaGetSymbolAddress((void**)&wkvbl, g_wkvbl);
    cudaGetSymbolAddress((void**)&woh, g_woh);     cudaGetSymbolAddress((void**)&wol, g_wol);
    cudaGetSymbolAddress((void**)&qakvf, g_qakv_f);
    cudaGetSymbolAddress((void**)&qah, g_qah);     cudaGetSymbolAddress((void**)&qal, g_qal);
    cudaGetSymbolAddress((void**)&qh, g_qh);       cudaGetSymbolAddress((void**)&ql, g_ql);
    cudaGetSymbolAddress((void**)&kfh, g_kfh);     cudaGetSymbolAddress((void**)&kfl, g_kfl);
    cudaGetSymbolAddress((void**)&kveh, g_kveh);   cudaGetSymbolAddress((void**)&kvel, g_kvel);
    cudaGetSymbolAddress((void**)&vTh, g_vTh);     cudaGetSymbolAddress((void**)&vTl, g_vTl);
    cudaGetSymbolAddress((void**)&Ph, g_Ph);       cudaGetSymbolAddress((void**)&Pl, g_Pl);
    cudaGetSymbolAddress((void**)&ps, g_ps);       cudaGetSymbolAddress((void**)&inv, g_inv);
    cudaGetSymbolAddress((void**)&o2h, g_o2h);     cudaGetSymbolAddress((void**)&o2l, g_o2l);

    cudaFuncSetAttribute(gemm_bf3<0>, cudaFuncAttributeMaxDynamicSharedMemorySize, SMEM_BYTES);
    cudaFuncSetAttribute(gemm_bf3<1>, cudaFuncAttributeMaxDynamicSharedMemorySize, SMEM_BYTES);
    cudaFuncSetAttribute(gemm_bf3<2>, cudaFuncAttributeMaxDynamicSharedMemorySize, SMEM_BYTES);

    dim3 blk(256);
    dim3 tb(32, 8);

    // 0. split inputs + weights
    auto splits = [&](const float* s, bf16* h, bf16* l, long n) {
        const long n4 = n / 4;
        int gs = (int)min((n4 + 255) / 256, (long)4096);
        split_kernel<<<gs, blk>>>(s, h, l, n4);
    };
    splits(x,     xh,  xl,  (long)ROWS * DIM);
    splits(wq_a,  wch, wcl, (long)Q_LORA * DIM);
    splits(wkv_a, wch + (size_t)Q_LORA * DIM, wcl + (size_t)Q_LORA * DIM,
           (long)QKD * DIM);
    splits(wq_b,  wqbh, wqbl, (long)N_HEADS * QK_HEAD * Q_LORA);
    splits(wkv_b, wkvbh, wkvbl, (long)N_HEADS * 256 * KV_LORA);
    splits(wo,    woh,  wol,  (long)DIM * DIM);

    // 1. qakv = x @ [wq_a ; wkv_a]^T  (merged, f32 out)
    gemm_bf3<0><<<dim3(ROWS/256, (NCOMB + 127)/128, 1), blk, SMEM_BYTES>>>(
        xh, xl, wch, wcl, qakvf, nullptr, nullptr,
        ROWS, NCOMB, DIM, DIM, DIM, NCOMB, 0,0, 0,0, 0,0, 1, 1.f, 0);

    // 2. norms
    rmsnorm_qa_kernel<<<ROWS, blk>>>(q_norm_w);
    kv_process_kernel<<<ROWS, blk>>>(kv_norm_w, fcos, fsin);

    // 3. q = qa @ wq_b^T (split out)
    gemm_bf3<1><<<dim3(ROWS/256, (N_HEADS*QK_HEAD)/128, 1), blk, SMEM_BYTES>>>(
        qah, qal, wqbh, wqbl, nullptr, qh, ql,
        ROWS, N_HEADS*QK_HEAD, Q_LORA, Q_LORA, Q_LORA, N_HEADS*QK_HEAD,
        0,0, 0,0, 0,0, 1, 1.f, 0);

    // 4. rope(q_pe) in place
    q_rope_kernel<<<ROWS, 512>>>(fcos, fsin);

    // 5. kve = kf_c @ wkvb^T  (merged k/v, split out, col shift)
    gemm_bf3<1><<<dim3(SEQ/256, 2, NBH), blk, SMEM_BYTES>>>(
        kfh, kfl, wkvbh, wkvbl, nullptr, kveh, kvel,
        SEQ, 256, KV_LORA, QKD, KV_LORA, KVW,
        (long)SEQ*QKD, 0,
        0, (long)256*KV_LORA,
        (long)N_HEADS*SEQ*KVW, (long)SEQ*KVW,
        N_HEADS, 1.f, 4);

    // 6. broadcast k_pe
    kpe_fill_kernel<<<ROWS, 512>>>();

    // 7. transpose v -> vT
    transpose_bf2<<<dim3(SEQ/32, V_HEAD/32, NBH), tb>>>(
        kveh + 192, kvel + 192, vTh, vTl, KVW, SEQ,
        (long)SEQ*KVW, (long)V_HEAD*SEQ);

    // 8. P~ = exp(SCALE * q'.kve^T) (causal, split out + partial sums)
    gemm_bf3<2><<<dim3(SEQ/256, SEQ/128, NBH), blk, SMEM_BYTES>>>(
        qh, ql, kveh, kvel, ps, Ph, Pl,
        SEQ, SEQ, QK_HEAD, N_HEADS*QK_HEAD, KVW, SEQ,
        (long)SEQ*N_HEADS*QK_HEAD, QK_HEAD,
        (long)N_HEADS*SEQ*KVW, (long)SEQ*KVW,
        (long)N_HEADS*SEQ*SEQ, (long)SEQ*SEQ,
        N_HEADS, SCALE_F, 1);

    // 9. inverse row sums (deterministic fixed-order combine)
    rowsum_combine_kernel<<<NBH*SEQ/256, blk>>>();

    // 10. o2 = (P~ @ vT^T) * inv_rowsum  (causal K bound)
    gemm_bf3<1><<<dim3(SEQ/256, 1, NBH), blk, SMEM_BYTES>>>(
        Ph, Pl, vTh, vTl, inv, o2h, o2l,
        SEQ, V_HEAD, SEQ, SEQ, SEQ, DIM,
        (long)N_HEADS*SEQ*SEQ, (long)SEQ*SEQ,
        (long)N_HEADS*V_HEAD*SEQ, (long)V_HEAD*SEQ,
        (long)SEQ*DIM, V_HEAD,
        N_HEADS, 1.f, 2 | 8);

    // 11. out = o2 @ wo^T  (f32 out)
    gemm_bf3<0><<<dim3(ROWS/256, DIM/128, 1), blk, SMEM_BYTES>>>(
        o2h, o2l, woh, wol, out, nullptr, nullptr,
        ROWS, DIM, DIM, DIM, DIM, DIM, 0,0, 0,0, 0,0, 1, 1.f, 0);
}

// round 14
// speedup vs baseline: 1.1092x; 1.0864x over previous
#include <cuda_runtime.h>
#include <cuda_bf16.h>
#include <math.h>
#include <stdint.h>

// ---------------------------------------------------------------------------
// MLA forward. Split-bf16 3-term tensor-core GEMMs (Ah.Bh + Ah.Bl + Al.Bh).
// Round 14: GEMM geometry 128x128 CTA tile, 4 warps (2x2), warp tile 64x64
// (1:6 ldm:MMA ratio preserved), 128 threads, 81.9KB smem -> 2 CTAs/SM:
// cross-CTA overlap hides barriers/epilogues, wave tails halve.
// Round-13 pipeline retained: merged qa+kv GEMM, merged k/v GEMM, fused
// exp-softmax epilogue with deterministic partial sums, causal skipping,
// de-absorbed attention. PTX-stable on compute_103 (no tcgen05).
// ---------------------------------------------------------------------------

#define DIM     2048
#define N_HEADS 16
#define Q_LORA  1536
#define KV_LORA 512
#define NOPE    128
#define ROPE    64
#define V_HEAD  128
#define QK_HEAD 192
#define BATCH   2
#define SEQ     2048
#define ROWS    (BATCH * SEQ)
#define QKD     (KV_LORA + ROPE)        // 576
#define NBH     (BATCH * N_HEADS)       // 32
#define NCOMB   (Q_LORA + QKD)          // 2112
#define KVW     320                     // 128 nope + 64 rope + 128 v
#define SCALE_F 0.0721687836487032f
#define EPS_F   1e-6f

typedef __nv_bfloat16 bf16;

// ------------------------- scratch (device globals) -------------------------
__device__ __align__(256) bf16  g_xh    [(size_t)ROWS * DIM];
__device__ __align__(256) bf16  g_xl    [(size_t)ROWS * DIM];
__device__ __align__(256) bf16  g_wcombh[(size_t)NCOMB * DIM];
__device__ __align__(256) bf16  g_wcombl[(size_t)NCOMB * DIM];
__device__ __align__(256) bf16  g_wqbh  [(size_t)N_HEADS * QK_HEAD * Q_LORA];
__device__ __align__(256) bf16  g_wqbl  [(size_t)N_HEADS * QK_HEAD * Q_LORA];
__device__ __align__(256) bf16  g_wkvbh [(size_t)N_HEADS * 256 * KV_LORA];
__device__ __align__(256) bf16  g_wkvbl [(size_t)N_HEADS * 256 * KV_LORA];
__device__ __align__(256) bf16  g_woh   [(size_t)DIM * DIM];
__device__ __align__(256) bf16  g_wol   [(size_t)DIM * DIM];

__device__ __align__(256) float g_qakv_f[(size_t)ROWS * NCOMB];
__device__ __align__(256) bf16  g_qah   [(size_t)ROWS * Q_LORA];
__device__ __align__(256) bf16  g_qal   [(size_t)ROWS * Q_LORA];
__device__ __align__(256) bf16  g_qh    [(size_t)ROWS * N_HEADS * QK_HEAD];
__device__ __align__(256) bf16  g_ql    [(size_t)ROWS * N_HEADS * QK_HEAD];
__device__ __align__(256) bf16  g_kfh   [(size_t)ROWS * QKD];
__device__ __align__(256) bf16  g_kfl   [(size_t)ROWS * QKD];

__device__ __align__(256) bf16  g_kveh  [(size_t)NBH * SEQ * KVW];
__device__ __align__(256) bf16  g_kvel  [(size_t)NBH * SEQ * KVW];
__device__ __align__(256) bf16  g_vTh   [(size_t)NBH * V_HEAD * SEQ];
__device__ __align__(256) bf16  g_vTl   [(size_t)NBH * V_HEAD * SEQ];

__device__ __align__(256) bf16  g_Ph    [(size_t)NBH * SEQ * SEQ];
__device__ __align__(256) bf16  g_Pl    [(size_t)NBH * SEQ * SEQ];
__device__ __align__(256) float g_ps    [(size_t)NBH * SEQ * 16];
__device__ __align__(256) float g_inv   [(size_t)NBH * SEQ];
__device__ __align__(256) bf16  g_o2h   [(size_t)ROWS * DIM];
__device__ __align__(256) bf16  g_o2l   [(size_t)ROWS * DIM];

// ----------------------------- helpers --------------------------------------
__device__ __forceinline__ uint32_t smem_u32(const void* p) {
    uint32_t a;
    asm("{ .reg .u64 t; cvta.to.shared.u64 t, %1; cvt.u32.u64 %0, t; }"
        : "=r"(a) : "l"(p));
    return a;
}
__device__ __forceinline__ void cp16(uint32_t dst, const void* src) {
    asm volatile("cp.async.ca.shared.global [%0], [%1], 16;"
                 :: "r"(dst), "l"(src) : "memory");
}
#define CP_COMMIT() asm volatile("cp.async.commit_group;" ::: "memory")
#define CP_WAIT(n)  asm volatile("cp.async.wait_group %0;" :: "n"(n) : "memory")

__device__ __forceinline__ void ldm_x4(uint32_t* r, uint32_t addr) {
    asm volatile("ldmatrix.sync.aligned.m8n8.x4.shared.b16 {%0,%1,%2,%3}, [%4];"
                 : "=r"(r[0]), "=r"(r[1]), "=r"(r[2]), "=r"(r[3]) : "r"(addr));
}
__device__ __forceinline__ void mma_bf16(float* d, const uint32_t* a,
                                         const uint32_t* b) {
    asm volatile(
        "mma.sync.aligned.m16n8k16.row.col.f32.bf16.bf16.f32 "
        "{%0,%1,%2,%3}, {%4,%5,%6,%7}, {%8,%9}, {%0,%1,%2,%3};"
        : "+f"(d[0]), "+f"(d[1]), "+f"(d[2]), "+f"(d[3])
        : "r"(a[0]), "r"(a[1]), "r"(a[2]), "r"(a[3]), "r"(b[0]), "r"(b[1]));
}
__device__ __forceinline__ void bsplit(float x, bf16& h, bf16& l) {
    h = __float2bfloat16_rn(x);
    l = __float2bfloat16_rn(x - __bfloat162float(h));
}

// ----------------------- GEMM: C = alpha * A.B^T ----------------------------
// CTA tile 128x128, BK=32, 128 threads, warp tile 64x64 (2m x 2n warps).
// OUTM=0: C f32. OUTM=1: split bf16 (C may carry inv-rowsum, mode bit3).
// OUTM=2: exp epilogue -> split bf16 P + per-(row,ntile) partial sums in C.
// mode bit0: causal tile skip (n0 > m0); bit1: causal K bound (m0+128);
// bit2: col+=64 if col>=128 (unified k/v layout); bit3: scale rows by C[row].
#define ROWB 80
#define AT_B (128 * ROWB)                // 10240
#define BT_B (128 * ROWB)                // 10240
#define STG_B (2 * AT_B + 2 * BT_B)      // 40960
#define SMEM_BYTES (2 * STG_B)           // 81920 -> 2 CTAs/SM

__device__ __forceinline__ void load_tileA(uint32_t dst, const bf16* __restrict__ src,
                                           int ld, int k0, int tid) {
#pragma unroll
    for (int it = 0; it < 4; it++) {
        const int idx = tid + it * 128;
        const int row = idx >> 2, seg = idx & 3;
        cp16(dst + (uint32_t)(row * ROWB + seg * 16),
             src + (size_t)row * ld + k0 + seg * 8);
    }
}
__device__ __forceinline__ void load_tileB(uint32_t dst, const bf16* __restrict__ src,
                                           int ld, int k0, int limit, int tid) {
#pragma unroll
    for (int it = 0; it < 4; it++) {
        const int idx = tid + it * 128;
        const int row = idx >> 2, seg = idx & 3;
        const uint32_t d = dst + (uint32_t)(row * ROWB + seg * 16);
        if (row < limit) {
            cp16(d, src + (size_t)row * ld + k0 + seg * 8);
        } else {
            asm volatile("st.shared.v4.b32 [%0], {%1,%1,%1,%1};"
                         :: "r"(d), "r"(0) : "memory");
        }
    }
}
__device__ __forceinline__ void load_stage(uint32_t base,
                                           const bf16* Ath, const bf16* Atl,
                                           const bf16* Bth, const bf16* Btl,
                                           int lda, int ldb, int k0, int nlim, int tid) {
    load_tileA(base,                Ath, lda, k0, tid);
    load_tileA(base + AT_B,         Atl, lda, k0, tid);
    load_tileB(base + 2 * AT_B,        Bth, ldb, k0, nlim, tid);
    load_tileB(base + 2 * AT_B + BT_B, Btl, ldb, k0, nlim, tid);
}

template <int OUTM>
__global__ void __launch_bounds__(128)
gemm_bf3(const bf16* __restrict__ Ah, const bf16* __restrict__ Al,
         const bf16* __restrict__ Bh, const bf16* __restrict__ Bl,
         float* __restrict__ C, bf16* __restrict__ Ch, bf16* __restrict__ Cl,
         int M, int N, int K, int lda, int ldb, int ldc,
         long sAo, long sAi, long sBo, long sBi, long sCo, long sCi,
         int inner, float alpha, int mode)
{
    const int m0 = blockIdx.x * 128, n0 = blockIdx.y * 128;
    if ((mode & 1) && n0 > m0) return;

    extern __shared__ char smem[];
    __shared__ float sred[2][128];
    const uint32_t sb = smem_u32(smem);
    const int tid = threadIdx.x, lane = tid & 31, wid = tid >> 5;
    const int wm = wid >> 1, wn = wid & 1;      // 2(m) x 2(n) warps, 64x64 tiles
    const int g = lane >> 2, tig = lane & 3;

    const int z = blockIdx.z, zo = z / inner, zi = z - zo * inner;
    const long ofA = (long)zo * sAo + (long)zi * sAi;
    const long ofB = (long)zo * sBo + (long)zi * sBi;
    const long ofC = (long)zo * sCo + (long)zi * sCi;
    Ah += ofA; Al += ofA;
    Bh += ofB; Bl += ofB;

    const bf16* Ath = Ah + (size_t)m0 * lda;
    const bf16* Atl = Al + (size_t)m0 * lda;
    const bf16* Bth = Bh + (size_t)n0 * ldb;
    const bf16* Btl = Bl + (size_t)n0 * ldb;
    const int nlim = min(128, N - n0);

    float acc[4][8][4];
#pragma unroll
    for (int i = 0; i < 4; i++)
#pragma unroll
        for (int j = 0; j < 8; j++)
#pragma unroll
            for (int r = 0; r < 4; r++) acc[i][j][r] = 0.f;

    const int Keff = (mode & 2) ? min(K, m0 + 128) : K;
    const int nch = Keff >> 5;

    load_stage(sb, Ath, Atl, Bth, Btl, lda, ldb, 0, nlim, tid);
    CP_COMMIT();

    const uint32_t aoffL = (uint32_t)((wm * 64 + (lane & 15)) * ROWB + (lane >> 4) * 16);
    const uint32_t boffL = (uint32_t)((wn * 64 + ((lane >> 4) & 1) * 8 + (lane & 7)) * ROWB
                                      + ((lane >> 3) & 1) * 16);

    for (int c = 0; c < nch; c++) {
        if (c + 1 < nch) {
            load_stage(sb + ((c + 1) & 1) * STG_B, Ath, Atl, Bth, Btl,
                       lda, ldb, (c + 1) << 5, nlim, tid);
            CP_COMMIT();
            CP_WAIT(1);
        } else {
            CP_WAIT(0);
        }
        __syncthreads();

        const uint32_t base = sb + (c & 1) * STG_B;
        const uint32_t aA = base + aoffL;
        const uint32_t bA = base + 2 * AT_B + boffL;

#pragma unroll
        for (int ks = 0; ks < 2; ks++) {
            uint32_t bh[4][4], bl[4][4];
#pragma unroll
            for (int jj = 0; jj < 4; jj++) {
                ldm_x4(bh[jj], bA + ks * 32 + jj * 16 * ROWB);
                ldm_x4(bl[jj], bA + BT_B + ks * 32 + jj * 16 * ROWB);
            }
#pragma unroll
            for (int i = 0; i < 4; i++) {
                uint32_t ahf[4], alf[4];
                ldm_x4(ahf, aA + ks * 32 + i * 16 * ROWB);
                ldm_x4(alf, aA + AT_B + ks * 32 + i * 16 * ROWB);
#pragma unroll
                for (int j = 0; j < 8; j++) {
                    const uint32_t* bhp = &bh[j >> 1][(j & 1) * 2];
                    const uint32_t* blp = &bl[j >> 1][(j & 1) * 2];
                    mma_bf16(acc[i][j], alf, bhp);
                    mma_bf16(acc[i][j], ahf, blp);
                    mma_bf16(acc[i][j], ahf, bhp);
                }
            }
        }
        __syncthreads();
    }

    if (OUTM == 2) {
        // exp epilogue: unnormalized softmax numerators + deterministic
        // per-(row, n-tile) partial sums. M == SEQ here; r0 is the s index.
        float* ps = C + (size_t)z * SEQ * 16;
        const int ntile = n0 >> 7;
#pragma unroll
        for (int i = 0; i < 4; i++) {
            const int r0 = m0 + wm * 64 + i * 16 + g;
            float s0 = 0.f, s1 = 0.f;
#pragma unroll
            for (int j = 0; j < 8; j++) {
                const int col = n0 + wn * 64 + j * 8 + tig * 2;
                const float e0 = (col     <= r0)     ? __expf(alpha * acc[i][j][0]) : 0.f;
                const float e1 = (col + 1 <= r0)     ? __expf(alpha * acc[i][j][1]) : 0.f;
                const float e2 = (col     <= r0 + 8) ? __expf(alpha * acc[i][j][2]) : 0.f;
                const float e3 = (col + 1 <= r0 + 8) ? __expf(alpha * acc[i][j][3]) : 0.f;
                s0 += e0 + e1; s1 += e2 + e3;
                bf16 h0, l0, h1, l1, h2, l2, h3, l3;
                bsplit(e0, h0, l0); bsplit(e1, h1, l1);
                bsplit(e2, h2, l2); bsplit(e3, h3, l3);
                *reinterpret_cast<__nv_bfloat162*>(Ch + ofC + (size_t)r0 * ldc + col)
                    = __nv_bfloat162(h0, h1);
                *reinterpret_cast<__nv_bfloat162*>(Cl + ofC + (size_t)r0 * ldc + col)
                    = __nv_bfloat162(l0, l1);
                *reinterpret_cast<__nv_bfloat162*>(Ch + ofC + (size_t)(r0 + 8) * ldc + col)
                    = __nv_bfloat162(h2, h3);
                *reinterpret_cast<__nv_bfloat162*>(Cl + ofC + (size_t)(r0 + 8) * ldc + col)
                    = __nv_bfloat162(l2, l3);
            }
            s0 += __shfl_xor_sync(0xffffffffu, s0, 1);
            s0 += __shfl_xor_sync(0xffffffffu, s0, 2);
            s1 += __shfl_xor_sync(0xffffffffu, s1, 1);
            s1 += __shfl_xor_sync(0xffffffffu, s1, 2);
            if (tig == 0) {
                sred[wn][wm * 64 + i * 16 + g]     = s0;
                sred[wn][wm * 64 + i * 16 + g + 8] = s1;
            }
        }
        __syncthreads();
        ps[(size_t)(m0 + tid) * 16 + ntile] = sred[0][tid] + sred[1][tid];
        return;
    }

    // standard epilogues
#pragma unroll
    for (int i = 0; i < 4; i++) {
        const int r0 = m0 + wm * 64 + i * 16 + g;
        float sc0 = alpha, sc1 = alpha;
        if (OUTM == 1 && (mode & 8)) {
            const float* invp = C + (size_t)z * SEQ;
            sc0 = invp[r0]; sc1 = invp[r0 + 8];
        }
#pragma unroll
        for (int j = 0; j < 8; j++) {
            const int col = n0 + wn * 64 + j * 8 + tig * 2;
            if (col >= N) continue;
            const int ocol = ((mode & 4) && col >= 128) ? col + 64 : col;
            const float c0 = sc0 * acc[i][j][0], c1 = sc0 * acc[i][j][1];
            const float c2 = sc1 * acc[i][j][2], c3 = sc1 * acc[i][j][3];
            if (OUTM == 0) {
                float* p0 = C + ofC + (size_t)r0 * ldc + ocol;
                float* p1 = C + ofC + (size_t)(r0 + 8) * ldc + ocol;
                if (col + 1 < N) {
                    *reinterpret_cast<float2*>(p0) = make_float2(c0, c1);
                    *reinterpret_cast<float2*>(p1) = make_float2(c2, c3);
                } else { p0[0] = c0; p1[0] = c2; }
            } else {
                bf16 h0, l0, h1, l1, h2, l2, h3, l3;
                bsplit(c0, h0, l0); bsplit(c1, h1, l1);
                bsplit(c2, h2, l2); bsplit(c3, h3, l3);
                *reinterpret_cast<__nv_bfloat162*>(Ch + ofC + (size_t)r0 * ldc + ocol)
                    = __nv_bfloat162(h0, h1);
                *reinterpret_cast<__nv_bfloat162*>(Cl + ofC + (size_t)r0 * ldc + ocol)
                    = __nv_bfloat162(l0, l1);
                *reinterpret_cast<__nv_bfloat162*>(Ch + ofC + (size_t)(r0 + 8) * ldc + ocol)
                    = __nv_bfloat162(h2, h3);
                *reinterpret_cast<__nv_bfloat162*>(Cl + ofC + (size_t)(r0 + 8) * ldc + ocol)
                    = __nv_bfloat162(l2, l3);
            }
        }
    }
}

// ----------------- combine partial sums -> inverse row sums -----------------
__global__ void __launch_bounds__(256)
rowsum_combine_kernel()
{
    const long row = (long)blockIdx.x * 256 + threadIdx.x;  // [bh][s]
    const int s = (int)(row & (SEQ - 1));
    const int nt = (s >> 7) + 1;              // 128-col n-tiles written
    const float* ps = g_ps + row * 16;
    float sum = 0.f;
    for (int j = 0; j < nt; j++) sum += ps[j];
    g_inv[row] = 1.0f / sum;
}

// ---------------------- elementwise split f32 -> bf16 hi/lo ------------------
__global__ void __launch_bounds__(256)
split_kernel(const float* __restrict__ src, bf16* __restrict__ h,
             bf16* __restrict__ l, long n4)
{
    const long stride = (long)gridDim.x * blockDim.x;
    for (long i = blockIdx.x * (long)blockDim.x + threadIdx.x; i < n4; i += stride) {
        const float4 v = reinterpret_cast<const float4*>(src)[i];
        bf16 h0, l0, h1, l1, h2, l2, h3, l3;
        bsplit(v.x, h0, l0); bsplit(v.y, h1, l1);
        bsplit(v.z, h2, l2); bsplit(v.w, h3, l3);
        reinterpret_cast<__nv_bfloat162*>(h)[i * 2]     = __nv_bfloat162(h0, h1);
        reinterpret_cast<__nv_bfloat162*>(h)[i * 2 + 1] = __nv_bfloat162(h2, h3);
        reinterpret_cast<__nv_bfloat162*>(l)[i * 2]     = __nv_bfloat162(l0, l1);
        reinterpret_cast<__nv_bfloat162*>(l)[i * 2 + 1] = __nv_bfloat162(l2, l3);
    }
}

// ------------------- dual bf16 transpose (32x32 tiles) ----------------------
__global__ void __launch_bounds__(256)
transpose_bf2(const bf16* __restrict__ sh, const bf16* __restrict__ sl,
              bf16* __restrict__ dh, bf16* __restrict__ dl,
              int lds, int ldd, long sS, long sD)
{
    __shared__ float th[32][33], tl[32][33];
    const int z = blockIdx.z;
    sh += (long)z * sS; sl += (long)z * sS;
    dh += (long)z * sD; dl += (long)z * sD;
    const int r0 = blockIdx.x * 32, c0 = blockIdx.y * 32;
    const int tx = threadIdx.x, ty = threadIdx.y;
#pragma unroll
    for (int i = 0; i < 4; i++) {
        const long s = (long)(r0 + ty + 8 * i) * lds + c0 + tx;
        th[ty + 8 * i][tx] = __bfloat162float(sh[s]);
        tl[ty + 8 * i][tx] = __bfloat162float(sl[s]);
    }
    __syncthreads();
#pragma unroll
    for (int i = 0; i < 4; i++) {
        const long d = (long)(c0 + ty + 8 * i) * ldd + r0 + tx;
        dh[d] = __float2bfloat16_rn(th[tx][ty + 8 * i]);
        dl[d] = __float2bfloat16_rn(tl[tx][ty + 8 * i]);
    }
}

// --------------------------- rmsnorm: f32 -> split --------------------------
__global__ void __launch_bounds__(256)
rmsnorm_qa_kernel(const float* __restrict__ w)
{
    const long row = blockIdx.x;
    const float* p = g_qakv_f + row * NCOMB;
    const int tid = threadIdx.x;
    float v[6];
    float ss = 0.f;
#pragma unroll
    for (int i = 0; i < 6; i++) { v[i] = p[tid + i * 256]; ss += v[i] * v[i]; }
    __shared__ float red[256];
    red[tid] = ss; __syncthreads();
    for (int o = 128; o > 0; o >>= 1) {
        if (tid < o) red[tid] += red[tid + o];
        __syncthreads();
    }
    const float scale = rsqrtf(red[0] / (float)Q_LORA + EPS_F);
#pragma unroll
    for (int i = 0; i < 6; i++) {
        const int c = tid + i * 256;
        bf16 h, l;
        bsplit(v[i] * scale * w[c], h, l);
        g_qah[row * Q_LORA + c] = h;
        g_qal[row * Q_LORA + c] = l;
    }
}

// ------------- kv_process: qakv cols 1536:2112 -> split kf ------------------
__global__ void __launch_bounds__(256)
kv_process_kernel(const float* __restrict__ kv_norm_w,
                  const float* __restrict__ fcos,
                  const float* __restrict__ fsin)
{
    const long row = blockIdx.x;
    const int pos = (int)(row & (SEQ - 1));
    const float* src = g_qakv_f + row * NCOMB + Q_LORA;
    const int tid = threadIdx.x;

    const float v0 = src[tid], v1 = src[tid + 256];
    __shared__ float red[256];
    red[tid] = v0 * v0 + v1 * v1; __syncthreads();
    for (int o = 128; o > 0; o >>= 1) {
        if (tid < o) red[tid] += red[tid + o];
        __syncthreads();
    }
    const float scale = rsqrtf(red[0] / (float)KV_LORA + EPS_F);
    bf16 h, l;
    bsplit(v0 * scale * kv_norm_w[tid], h, l);
    g_kfh[row * QKD + tid] = h; g_kfl[row * QKD + tid] = l;
    bsplit(v1 * scale * kv_norm_w[tid + 256], h, l);
    g_kfh[row * QKD + tid + 256] = h; g_kfl[row * QKD + tid + 256] = l;

    if (tid < 32) {
        const float x0 = src[KV_LORA + 2 * tid];
        const float x1 = src[KV_LORA + 2 * tid + 1];
        const float c = fcos[pos * 32 + tid];
        const float s = fsin[pos * 32 + tid];
        bsplit(x0 * c - x1 * s, h, l);
        g_kfh[row * QKD + KV_LORA + 2 * tid] = h;
        g_kfl[row * QKD + KV_LORA + 2 * tid] = l;
        bsplit(x0 * s + x1 * c, h, l);
        g_kfh[row * QKD + KV_LORA + 2 * tid + 1] = h;
        g_kfl[row * QKD + KV_LORA + 2 * tid + 1] = l;
    }
}

// ------------- q rope (in place on split q) ---------------------------------
__global__ void __launch_bounds__(512)
q_rope_kernel(const float* __restrict__ fcos, const float* __restrict__ fsin)
{
    const long row = blockIdx.x;
    const int pos = (int)(row & (SEQ - 1));
    const int h = threadIdx.x / 32;
    const int i = threadIdx.x % 32;

    const long si = row * (N_HEADS * QK_HEAD) + h * QK_HEAD + NOPE + 2 * i;
    const float x0 = __bfloat162float(g_qh[si])     + __bfloat162float(g_ql[si]);
    const float x1 = __bfloat162float(g_qh[si + 1]) + __bfloat162float(g_ql[si + 1]);
    const float c = fcos[pos * 32 + i];
    const float s = fsin[pos * 32 + i];
    bf16 hh, ll;
    bsplit(x0 * c - x1 * s, hh, ll);
    g_qh[si] = hh; g_ql[si] = ll;
    bsplit(x0 * s + x1 * c, hh, ll);
    g_qh[si + 1] = hh; g_ql[si + 1] = ll;
}

// ------------- broadcast k_pe into kve cols 128:192 -------------------------
__global__ void __launch_bounds__(512)
kpe_fill_kernel()
{
    const long row = blockIdx.x;
    const int b = (int)(row >> 11);
    const int t = (int)(row & (SEQ - 1));
    const long src = row * QKD + KV_LORA;
#pragma unroll
    for (int it = 0; it < 2; it++) {
        const int e = threadIdx.x + it * 512;
        const int h = e >> 6, j = e & 63;
        const long dst = ((long)(b * N_HEADS + h) * SEQ + t) * KVW + NOPE + j;
        g_kveh[dst] = g_kfh[src + j];
        g_kvel[dst] = g_kfl[src + j];
    }
}

// ---------------------------------------------------------------------------
extern "C" void kernel_launch(void* const* d_in, const int* in_sizes, int n_in,
                              void* d_out, int out_size)
{
    const float* x         = (const float*)d_in[0];
    const float* fcos      = (const float*)d_in[1];
    const float* fsin      = (const float*)d_in[2];
    // d_in[3] = mask (unused; causal mask computed inline, exact)
    const float* wq_a      = (const float*)d_in[4];
    const float* q_norm_w  = (const float*)d_in[5];
    const float* wq_b      = (const float*)d_in[6];
    const float* wkv_a     = (const float*)d_in[7];
    const float* kv_norm_w = (const float*)d_in[8];
    const float* wkv_b     = (const float*)d_in[9];
    const float* wo        = (const float*)d_in[10];
    float* out = (float*)d_out;

    bf16 *xh, *xl, *wch, *wcl, *wqbh, *wqbl, *wkvbh, *wkvbl, *woh, *wol;
    bf16 *qah, *qal, *qh, *ql, *kfh, *kfl, *kveh, *kvel, *vTh, *vTl;
    bf16 *Ph, *Pl, *o2h, *o2l;
    float *qakvf, *ps, *inv;
    cudaGetSymbolAddress((void**)&xh, g_xh);       cudaGetSymbolAddress((void**)&xl, g_xl);
    cudaGetSymbolAddress((void**)&wch, g_wcombh);  cudaGetSymbolAddress((void**)&wcl, g_wcombl);
    cudaGetSymbolAddress((void**)&wqbh, g_wqbh);   cudaGetSymbolAddress((void**)&wqbl, g_wqbl);
    cudaGetSymbolAddress((void**)&wkvbh, g_wkvbh); cudaGetSymbolAddress((void**)&wkvbl, g_wkvbl);
    cudaGetSymbolAddress((void**)&woh, g_woh);     cudaGetSymbolAddress((void**)&wol, g_wol);
    cudaGetSymbolAddress((void**)&qakvf, g_qakv_f);
    cudaGetSymbolAddress((void**)&qah, g_qah);     cudaGetSymbolAddress((void**)&qal, g_qal);
    cudaGetSymbolAddress((void**)&qh, g_qh);       cudaGetSymbolAddress((void**)&ql, g_ql);
    cudaGetSymbolAddress((void**)&kfh, g_kfh);     cudaGetSymbolAddress((void**)&kfl, g_kfl);
    cudaGetSymbolAddress((void**)&kveh, g_kveh);   cudaGetSymbolAddress((void**)&kvel, g_kvel);
    cudaGetSymbolAddress((void**)&vTh, g_vTh);     cudaGetSymbolAddress((void**)&vTl, g_vTl);
    cudaGetSymbolAddress((void**)&Ph, g_Ph);       cudaGetSymbolAddress((void**)&Pl, g_Pl);
    cudaGetSymbolAddress((void**)&ps, g_ps);       cudaGetSymbolAddress((void**)&inv, g_inv);
    cudaGetSymbolAddress((void**)&o2h, g_o2h);     cudaGetSymbolAddress((void**)&o2l, g_o2l);

    cudaFuncSetAttribute(gemm_bf3<0>, cudaFuncAttributeMaxDynamicSharedMemorySize, SMEM_BYTES);
    cudaFuncSetAttribute(gemm_bf3<1>, cudaFuncAttributeMaxDynamicSharedMemorySize, SMEM_BYTES);
    cudaFuncSetAttribute(gemm_bf3<2>, cudaFuncAttributeMaxDynamicSharedMemorySize, SMEM_BYTES);

    dim3 blk(256);
    dim3 gblk(128);
    dim3 tb(32, 8);

    // 0. split inputs + weights
    auto splits = [&](const float* s, bf16* h, bf16* l, long n) {
        const long n4 = n / 4;
        int gs = (int)min((n4 + 255) / 256, (long)4096);
        split_kernel<<<gs, blk>>>(s, h, l, n4);
    };
    splits(x,     xh,  xl,  (long)ROWS * DIM);
    splits(wq_a,  wch, wcl, (long)Q_LORA * DIM);
    splits(wkv_a, wch + (size_t)Q_LORA * DIM, wcl + (size_t)Q_LORA * DIM,
           (long)QKD * DIM);
    splits(wq_b,  wqbh, wqbl, (long)N_HEADS * QK_HEAD * Q_LORA);
    splits(wkv_b, wkvbh, wkvbl, (long)N_HEADS * 256 * KV_LORA);
    splits(wo,    woh,  wol,  (long)DIM * DIM);

    // 1. qakv = x @ [wq_a ; wkv_a]^T  (merged, f32 out)
    gemm_bf3<0><<<dim3(ROWS/128, (NCOMB + 127)/128, 1), gblk, SMEM_BYTES>>>(
        xh, xl, wch, wcl, qakvf, nullptr, nullptr,
        ROWS, NCOMB, DIM, DIM, DIM, NCOMB, 0,0, 0,0, 0,0, 1, 1.f, 0);

    // 2. norms
    rmsnorm_qa_kernel<<<ROWS, blk>>>(q_norm_w);
    kv_process_kernel<<<ROWS, blk>>>(kv_norm_w, fcos, fsin);

    // 3. q = qa @ wq_b^T (split out)
    gemm_bf3<1><<<dim3(ROWS/128, (N_HEADS*QK_HEAD)/128, 1), gblk, SMEM_BYTES>>>(
        qah, qal, wqbh, wqbl, nullptr, qh, ql,
        ROWS, N_HEADS*QK_HEAD, Q_LORA, Q_LORA, Q_LORA, N_HEADS*QK_HEAD,
        0,0, 0,0, 0,0, 1, 1.f, 0);

    // 4. rope(q_pe) in place
    q_rope_kernel<<<ROWS, 512>>>(fcos, fsin);

    // 5. kve = kf_c @ wkvb^T  (merged k/v, split out, col shift)
    gemm_bf3<1><<<dim3(SEQ/128, 2, NBH), gblk, SMEM_BYTES>>>(
        kfh, kfl, wkvbh, wkvbl, nullptr, kveh, kvel,
        SEQ, 256, KV_LORA, QKD, KV_LORA, KVW,
        (long)SEQ*QKD, 0,
        0, (long)256*KV_LORA,
        (long)N_HEADS*SEQ*KVW, (long)SEQ*KVW,
        N_HEADS, 1.f, 4);

    // 6. broadcast k_pe
    kpe_fill_kernel<<<ROWS, 512>>>();

    // 7. transpose v -> vT
    transpose_bf2<<<dim3(SEQ/32, V_HEAD/32, NBH), tb>>>(
        kveh + 192, kvel + 192, vTh, vTl, KVW, SEQ,
        (long)SEQ*KVW, (long)V_HEAD*SEQ);

    // 8. P~ = exp(SCALE * q'.kve^T) (causal, split out + partial sums)
    gemm_bf3<2><<<dim3(SEQ/128, SEQ/128, NBH), gblk, SMEM_BYTES>>>(
        qh, ql, kveh, kvel, ps, Ph, Pl,
        SEQ, SEQ, QK_HEAD, N_HEADS*QK_HEAD, KVW, SEQ,
        (long)SEQ*N_HEADS*QK_HEAD, QK_HEAD,
        (long)N_HEADS*SEQ*KVW, (long)SEQ*KVW,
        (long)N_HEADS*SEQ*SEQ, (long)SEQ*SEQ,
        N_HEADS, SCALE_F, 1);

    // 9. inverse row sums (deterministic fixed-order combine)
    rowsum_combine_kernel<<<NBH*SEQ/256, blk>>>();

    // 10. o2 = (P~ @ vT^T) * inv_rowsum  (causal K bound)
    gemm_bf3<1><<<dim3(SEQ/128, 1, NBH), gblk, SMEM_BYTES>>>(
        Ph, Pl, vTh, vTl, inv, o2h, o2l,
        SEQ, V_HEAD, SEQ, SEQ, SEQ, DIM,
        (long)N_HEADS*SEQ*SEQ, (long)SEQ*SEQ,
        (long)N_HEADS*V_HEAD*SEQ, (long)V_HEAD*SEQ,
        (long)SEQ*DIM, V_HEAD,
        N_HEADS, 1.f, 2 | 8);

    // 11. out = o2 @ wo^T  (f32 out)
    gemm_bf3<0><<<dim3(ROWS/128, DIM/128, 1), gblk, SMEM_BYTES>>>(
        o2h, o2l, woh, wol, out, nullptr, nullptr,
        ROWS, DIM, DIM, DIM, DIM, DIM, 0,0, 0,0, 0,0, 1, 1.f, 0);
}